// round 6
// baseline (speedup 1.0000x reference)
#include <cuda_runtime.h>
#include <cuda_bf16.h>
#include <math.h>
#include <cstdint>

#define BATCH 4
#define CDIM  256
#define NSP   4096
#define BN2   16777216
#define KTOT  768          // [hi | lo | hi] x [hi | hi | lo]
#define NCHUNK 12          // K chunks of 64

// ---------------------------------------------------------------------------
// Device scratch
// ---------------------------------------------------------------------------
__device__ float g_rowsum[BATCH * NSP];
__device__ float g_colsum[BATCH * NSP];
__device__ __nv_bfloat16 g_P[(size_t)BATCH * NSP * KTOT];
__device__ __nv_bfloat16 g_Q[(size_t)BATCH * NSP * KTOT];
// top-3 partials
__device__ float g_cpart[BATCH * 32 * 3 * NSP];   // [b][rowblock][3][col]
__device__ float g_rpart[BATCH * 8  * 3 * NSP];   // [b][colchunk][3][row]

// ---------------------------------------------------------------------------
// PTX helpers (sm_80-compatible: cp.async, ldmatrix, mma.sync)
// ---------------------------------------------------------------------------
__device__ __forceinline__ uint32_t smem_u32(const void* p) {
    uint32_t a;
    asm("{ .reg .u64 t; cvta.to.shared.u64 t, %1; cvt.u32.u64 %0, t; }"
        : "=r"(a) : "l"(p));
    return a;
}
__device__ __forceinline__ void cp16(uint32_t s, const void* g) {
    asm volatile("cp.async.cg.shared.global [%0], [%1], 16;" :: "r"(s), "l"(g));
}
__device__ __forceinline__ void cp_commit() {
    asm volatile("cp.async.commit_group;");
}
template <int N>
__device__ __forceinline__ void cp_wait() {
    asm volatile("cp.async.wait_group %0;" :: "n"(N));
}
__device__ __forceinline__ void ldmx4(uint32_t* r, uint32_t addr) {
    asm volatile("ldmatrix.sync.aligned.m8n8.x4.shared.b16 {%0,%1,%2,%3}, [%4];"
                 : "=r"(r[0]), "=r"(r[1]), "=r"(r[2]), "=r"(r[3]) : "r"(addr));
}
__device__ __forceinline__ void mma16816(float* d, const uint32_t* a, const uint32_t* b) {
    asm volatile(
        "mma.sync.aligned.m16n8k16.row.col.f32.bf16.bf16.f32 "
        "{%0,%1,%2,%3}, {%4,%5,%6,%7}, {%8,%9}, {%0,%1,%2,%3};"
        : "+f"(d[0]), "+f"(d[1]), "+f"(d[2]), "+f"(d[3])
        : "r"(a[0]), "r"(a[1]), "r"(a[2]), "r"(a[3]), "r"(b[0]), "r"(b[1]));
}

// ---------------------------------------------------------------------------
// Kernel 0: zero accumulators
// ---------------------------------------------------------------------------
__global__ void zero_sums_kernel() {
    int i = blockIdx.x * 256 + threadIdx.x;
    g_rowsum[i] = 0.0f;
    g_colsum[i] = 0.0f;
}

// ---------------------------------------------------------------------------
// Kernel 1: prep — L2-normalize, bf16 hi/lo split, K-major [m][768]
// ---------------------------------------------------------------------------
__global__ __launch_bounds__(256)
void prep_kernel(const float* __restrict__ xp, const float* __restrict__ xq) {
    __shared__ float tile[32][257];
    const int m0 = blockIdx.x * 32;
    const int b  = blockIdx.y;
    const int t  = threadIdx.x;
    const int w  = t >> 5, lane = t & 31;
    const bool isP = (blockIdx.z == 0);
    const float* src = isP ? xp : xq;
    __nv_bfloat16* dst = isP ? g_P : g_Q;

    #pragma unroll 8
    for (int it = 0; it < 32; it++) {
        int c = w + it * 8;
        tile[lane][c] = src[((size_t)b * CDIM + c) * NSP + m0 + lane];
    }
    __syncthreads();

    #pragma unroll
    for (int r = 0; r < 4; r++) {
        int row = w * 4 + r;
        float s = 0.0f;
        #pragma unroll
        for (int k = 0; k < 8; k++) {
            float v = tile[row][lane + 32 * k];
            s = fmaf(v, v, s);
        }
        #pragma unroll
        for (int off = 16; off > 0; off >>= 1)
            s += __shfl_down_sync(0xFFFFFFFFu, s, off);
        float invn = 1.0f / fmaxf(sqrtf(__shfl_sync(0xFFFFFFFFu, s, 0)), 1e-12f);

        size_t obase = ((size_t)b * NSP + m0 + row) * KTOT;
        #pragma unroll
        for (int k = 0; k < 8; k++) {
            int c = lane + 32 * k;
            float v = tile[row][c] * invn;
            __nv_bfloat16 hi = __float2bfloat16(v);
            __nv_bfloat16 lo = __float2bfloat16(v - __bfloat162float(hi));
            dst[obase + c] = hi;
            dst[obase + 256 + c] = isP ? lo : hi;
            dst[obase + 512 + c] = isP ? hi : lo;
        }
    }
}

// ---------------------------------------------------------------------------
// Kernel 2: HMMA GEMM (128x128, K=768) + exp epilogue  [R3 config, measured]
// ---------------------------------------------------------------------------
#define SMEM_BUFS  1024
#define SMEM_TOTAL (1024 + 4 * 16384)

__global__ __launch_bounds__(256, 2)
void gemm_exp_kernel(const float* __restrict__ alpha_p, float* __restrict__ out_e) {
    extern __shared__ char smem[];
    const uint32_t sbase = smem_u32(smem);
    float* srow = (float*)smem;
    float* scol = (float*)(smem + 512);

    const int t = threadIdx.x;
    const int w = t >> 5, lane = t & 31;
    const int b  = blockIdx.z;
    const int i0 = blockIdx.y * 128;
    const int j0 = blockIdx.x * 128;

    if (t < 128) { srow[t] = 0.0f; scol[t] = 0.0f; }

    const __nv_bfloat16* Abase = g_P + ((size_t)b * NSP + i0) * KTOT;
    const __nv_bfloat16* Bbase = g_Q + ((size_t)b * NSP + j0) * KTOT;

    auto load_chunk = [&](int c, int buf) {
        uint32_t aS = sbase + SMEM_BUFS + buf * 32768;
        uint32_t bS = aS + 16384;
        #pragma unroll
        for (int u = 0; u < 4; u++) {
            int f = t + 256 * u;
            uint32_t row = f >> 3, seg = f & 7;
            uint32_t off = row * 128 + ((seg ^ (row & 7)) << 4);
            cp16(aS + off, Abase + (size_t)row * KTOT + c * 64 + seg * 8);
            cp16(bS + off, Bbase + (size_t)row * KTOT + c * 64 + seg * 8);
        }
    };

    const int wm = w >> 2, wn = w & 3;
    const int r16 = lane & 15, ahi = lane >> 4;
    const int bn  = (lane & 7) + ((lane >> 4) << 3);
    const int bkl = (lane >> 3) & 1;

    float d[4][4][4] = {};

    load_chunk(0, 0);
    cp_commit();

    #pragma unroll 1
    for (int c = 0; c < NCHUNK; c++) {
        if (c < NCHUNK - 1) { load_chunk(c + 1, (c + 1) & 1); cp_commit(); }
        if (c < NCHUNK - 1) cp_wait<1>(); else cp_wait<0>();
        __syncthreads();

        uint32_t aS = sbase + SMEM_BUFS + (c & 1) * 32768;
        uint32_t bS = aS + 16384;

        #pragma unroll
        for (int kk = 0; kk < 4; kk++) {
            uint32_t afr[4][4];
            #pragma unroll
            for (int mt = 0; mt < 4; mt++) {
                uint32_t row = wm * 64 + mt * 16 + r16;
                uint32_t col = (((2 * kk + ahi) ^ (r16 & 7)) << 4);
                ldmx4(afr[mt], aS + row * 128 + col);
            }
            uint32_t bfr[4][2];
            #pragma unroll
            for (int np = 0; np < 2; np++) {
                uint32_t nrow = wn * 32 + np * 16 + bn;
                uint32_t col = (((2 * kk + bkl) ^ (bn & 7)) << 4);
                uint32_t q[4];
                ldmx4(q, bS + nrow * 128 + col);
                bfr[2 * np][0] = q[0]; bfr[2 * np][1] = q[1];
                bfr[2 * np + 1][0] = q[2]; bfr[2 * np + 1][1] = q[3];
            }
            #pragma unroll
            for (int mt = 0; mt < 4; mt++)
                #pragma unroll
                for (int nt = 0; nt < 4; nt++)
                    mma16816(d[mt][nt], afr[mt], bfr[nt]);
        }
        __syncthreads();
    }

    const float alpha = __ldg(alpha_p);
    const int g = lane >> 2, tg = lane & 3;
    float csum[4][2] = {};
    float* outb = out_e + (size_t)b * BN2;

    #pragma unroll
    for (int mt = 0; mt < 4; mt++) {
        float rs0 = 0.0f, rs1 = 0.0f;
        const int row0 = i0 + wm * 64 + mt * 16 + g;
        #pragma unroll
        for (int nt = 0; nt < 4; nt++) {
            float e0 = __expf(d[mt][nt][0] * alpha);
            float e1 = __expf(d[mt][nt][1] * alpha);
            float e2 = __expf(d[mt][nt][2] * alpha);
            float e3 = __expf(d[mt][nt][3] * alpha);
            rs0 += e0 + e1; rs1 += e2 + e3;
            csum[nt][0] += e0 + e2; csum[nt][1] += e1 + e3;
            const int colg = j0 + wn * 32 + nt * 8 + tg * 2;
            *(float2*)(outb + (size_t)row0 * NSP + colg)       = make_float2(e0, e1);
            *(float2*)(outb + (size_t)(row0 + 8) * NSP + colg) = make_float2(e2, e3);
        }
        rs0 += __shfl_xor_sync(0xFFFFFFFFu, rs0, 1);
        rs0 += __shfl_xor_sync(0xFFFFFFFFu, rs0, 2);
        rs1 += __shfl_xor_sync(0xFFFFFFFFu, rs1, 1);
        rs1 += __shfl_xor_sync(0xFFFFFFFFu, rs1, 2);
        if (tg == 0) {
            atomicAdd(&srow[wm * 64 + mt * 16 + g],     rs0);
            atomicAdd(&srow[wm * 64 + mt * 16 + g + 8], rs1);
        }
    }
    #pragma unroll
    for (int nt = 0; nt < 4; nt++)
        #pragma unroll
        for (int cc = 0; cc < 2; cc++) {
            float v = csum[nt][cc];
            v += __shfl_xor_sync(0xFFFFFFFFu, v, 4);
            v += __shfl_xor_sync(0xFFFFFFFFu, v, 8);
            v += __shfl_xor_sync(0xFFFFFFFFu, v, 16);
            if (g == 0) atomicAdd(&scol[wn * 32 + nt * 8 + tg * 2 + cc], v);
        }
    __syncthreads();
    if (t < 128) {
        atomicAdd(&g_rowsum[b * NSP + i0 + t], srow[t]);
        atomicAdd(&g_colsum[b * NSP + j0 + t], scol[t]);
    }
}

// ---------------------------------------------------------------------------
// top-3 helpers
// ---------------------------------------------------------------------------
__device__ __forceinline__ void top3_push(float v, float& v0, float& v1, float& v2) {
    if (v > v2) {
        if (v > v1) {
            v2 = v1;
            if (v > v0) { v1 = v0; v0 = v; } else { v1 = v; }
        } else v2 = v;
    }
}

// ---------------------------------------------------------------------------
// Kernel 3: finish — fused row pass + transpose + partial top-3s.
// Block = 128 rows x 512 cols (grid 8 x 32 x 4). Iterations of 128x64 tiles,
// double-buffered smem, ONE barrier per iteration, 8 LDG.128/thread prefetch.
// Thread phase-1 mapping: tc = t&15 (col quad), tr = t>>4; rows 16r+tr (r<8).
// Phase-2: warp w owns cols {8c+w}; per col, lane l covers rows l+32g.
// ---------------------------------------------------------------------------
#define FT_STRIDE 65
#define FT_TILE   (128 * FT_STRIDE)                 // floats per buffer
#define FIN_SMEM  ((512 + 2 * FT_TILE) * 4)         // 68608 bytes

__global__ __launch_bounds__(256, 2)
void finish_kernel(float* __restrict__ xcq, float* __restrict__ xcp) {
    extern __shared__ float fsm[];
    float* sinvc = fsm;                 // [512]
    float* tile0 = fsm + 512;           // [128][65]
    float* tile1 = tile0 + FT_TILE;

    const int b   = blockIdx.z;
    const int blk = blockIdx.y;           // rowblock 0..31
    const int cc  = blockIdx.x;           // colchunk 0..7
    const int i0  = blk * 128;
    const int j0  = cc * 512;
    const int t   = threadIdx.x;
    const int tc  = t & 15;               // col quad 0..15
    const int tr  = t >> 4;               // 0..15
    const int lane = t & 31, w = t >> 5;

    sinvc[t]       = 1.0f / g_colsum[b * NSP + j0 + t];
    sinvc[t + 256] = 1.0f / g_colsum[b * NSP + j0 + t + 256];

    float invr[8];
    #pragma unroll
    for (int r = 0; r < 8; r++)
        invr[r] = 1.0f / g_rowsum[b * NSP + i0 + 16 * r + tr];

    float rt0[8], rt1[8], rt2[8];
    #pragma unroll
    for (int r = 0; r < 8; r++) { rt0[r] = -1e30f; rt1[r] = -1e30f; rt2[r] = -1e30f; }

    float* srcb = xcq + (size_t)b * BN2 + (size_t)i0 * NSP;
    float* dstb = xcp + (size_t)b * BN2;

    // process loaded regs -> x values, write x_c, stage to tile, row top-3
    auto process = [&](float4* L, float* tl, int jt) {
        #pragma unroll
        for (int r = 0; r < 8; r++) {
            const int row = 16 * r + tr;
            const int cl  = (jt - j0) + tc * 4;
            float ir = invr[r];
            float x0 = L[r].x * L[r].x * ir * sinvc[cl + 0];
            float x1 = L[r].y * L[r].y * ir * sinvc[cl + 1];
            float x2 = L[r].z * L[r].z * ir * sinvc[cl + 2];
            float x3 = L[r].w * L[r].w * ir * sinvc[cl + 3];
            *(float4*)(srcb + (size_t)row * NSP + jt + tc * 4) = make_float4(x0, x1, x2, x3);
            float* tp = tl + row * FT_STRIDE + tc * 4;
            tp[0] = x0; tp[1] = x1; tp[2] = x2; tp[3] = x3;
            top3_push(x0, rt0[r], rt1[r], rt2[r]);
            top3_push(x1, rt0[r], rt1[r], rt2[r]);
            top3_push(x2, rt0[r], rt1[r], rt2[r]);
            top3_push(x3, rt0[r], rt1[r], rt2[r]);
        }
    };

    // prologue: iteration 0
    float4 L[8];
    {
        #pragma unroll
        for (int r = 0; r < 8; r++)
            L[r] = *(float4*)(srcb + (size_t)(16 * r + tr) * NSP + j0 + tc * 4);
        process(L, tile0, j0);
    }

    #pragma unroll 1
    for (int it = 0; it < 8; it++) {
        __syncthreads();
        float* tl = (it & 1) ? tile1 : tile0;
        const int jt = j0 + 64 * it;

        // prefetch next tile (hides under phase-2 smem work)
        if (it < 7) {
            const int jn = jt + 64;
            #pragma unroll
            for (int r = 0; r < 8; r++)
                L[r] = *(float4*)(srcb + (size_t)(16 * r + tr) * NSP + jn + tc * 4);
        }

        // phase 2: transposed writes + column top-3 partials
        #pragma unroll
        for (int c = 0; c < 8; c++) {
            const int colw = c * 8 + w;          // 0..63
            float c0 = -1e30f, c1 = -1e30f, c2 = -1e30f;
            #pragma unroll
            for (int g = 0; g < 4; g++) {
                float v = tl[(32 * g + lane) * FT_STRIDE + colw];
                dstb[(size_t)(jt + colw) * NSP + i0 + 32 * g + lane] = v;
                top3_push(v, c0, c1, c2);
            }
            #pragma unroll
            for (int off = 16; off > 0; off >>= 1) {
                float u0 = __shfl_xor_sync(0xFFFFFFFFu, c0, off);
                float u1 = __shfl_xor_sync(0xFFFFFFFFu, c1, off);
                float u2 = __shfl_xor_sync(0xFFFFFFFFu, c2, off);
                top3_push(u0, c0, c1, c2);
                top3_push(u1, c0, c1, c2);
                top3_push(u2, c0, c1, c2);
            }
            if (lane == 0) {
                const int base = (b * 32 + blk) * 3;
                g_cpart[(base + 0) * NSP + jt + colw] = c0;
                g_cpart[(base + 1) * NSP + jt + colw] = c1;
                g_cpart[(base + 2) * NSP + jt + colw] = c2;
            }
        }

        // phase 1 for next iteration into the other buffer
        if (it < 7) {
            float* tn = (it & 1) ? tile0 : tile1;
            process(L, tn, jt + 64);
        }
    }

    // row top-3 partials: merge across the 16 threads (tc) sharing each row
    #pragma unroll
    for (int r = 0; r < 8; r++) {
        float v0 = rt0[r], v1 = rt1[r], v2 = rt2[r];
        #pragma unroll
        for (int off = 8; off > 0; off >>= 1) {
            float u0 = __shfl_xor_sync(0xFFFFFFFFu, v0, off);
            float u1 = __shfl_xor_sync(0xFFFFFFFFu, v1, off);
            float u2 = __shfl_xor_sync(0xFFFFFFFFu, v2, off);
            top3_push(u0, v0, v1, v2);
            top3_push(u1, v0, v1, v2);
            top3_push(u2, v0, v1, v2);
        }
        if (tc == 0) {
            const int base = (b * 8 + cc) * 3;
            const int row = i0 + 16 * r + tr;
            g_rpart[(base + 0) * NSP + row] = v0;
            g_rpart[(base + 1) * NSP + row] = v1;
            g_rpart[(base + 2) * NSP + row] = v2;
        }
    }
}

// ---------------------------------------------------------------------------
// Kernel 4: reduce partials -> valp (z=0) and valq (z=1)
// ---------------------------------------------------------------------------
__global__ __launch_bounds__(256)
void topk_reduce_kernel(float* __restrict__ valp, float* __restrict__ valq) {
    const int b = blockIdx.y;
    const int j = blockIdx.x * 256 + threadIdx.x;
    float v0 = -1e30f, v1 = -1e30f, v2 = -1e30f;
    if (blockIdx.z == 0) {
        #pragma unroll 2
        for (int p = 0; p < 8; p++) {
            const int base = (b * 8 + p) * 3;
            top3_push(g_rpart[(base + 0) * NSP + j], v0, v1, v2);
            top3_push(g_rpart[(base + 1) * NSP + j], v0, v1, v2);
            top3_push(g_rpart[(base + 2) * NSP + j], v0, v1, v2);
        }
        valp[b * 3 * NSP + 0 * NSP + j] = v0;
        valp[b * 3 * NSP + 1 * NSP + j] = v1;
        valp[b * 3 * NSP + 2 * NSP + j] = v2;
    } else {
        #pragma unroll 2
        for (int p = 0; p < 32; p++) {
            const int base = (b * 32 + p) * 3;
            top3_push(g_cpart[(base + 0) * NSP + j], v0, v1, v2);
            top3_push(g_cpart[(base + 1) * NSP + j], v0, v1, v2);
            top3_push(g_cpart[(base + 2) * NSP + j], v0, v1, v2);
        }
        valq[b * 3 * NSP + 0 * NSP + j] = v0;
        valq[b * 3 * NSP + 1 * NSP + j] = v1;
        valq[b * 3 * NSP + 2 * NSP + j] = v2;
    }
}

// ---------------------------------------------------------------------------
extern "C" void kernel_launch(void* const* d_in, const int* in_sizes, int n_in,
                              void* d_out, int out_size) {
    const float* xp    = (const float*)d_in[0];
    const float* xq    = (const float*)d_in[1];
    const float* alpha = (const float*)d_in[2];

    float* valp = (float*)d_out;
    float* valq = valp + BATCH * 3 * NSP;
    float* xcp  = valq + BATCH * 3 * NSP;
    float* xcq  = xcp + (size_t)BATCH * BN2;

    cudaFuncSetAttribute(gemm_exp_kernel,
                         cudaFuncAttributeMaxDynamicSharedMemorySize, SMEM_TOTAL);
    cudaFuncSetAttribute(finish_kernel,
                         cudaFuncAttributeMaxDynamicSharedMemorySize, FIN_SMEM);

    zero_sums_kernel<<<64, 256>>>();
    prep_kernel<<<dim3(128, BATCH, 2), 256>>>(xp, xq);
    gemm_exp_kernel<<<dim3(32, 32, BATCH), 256, SMEM_TOTAL>>>(alpha, xcq);
    finish_kernel<<<dim3(8, 32, BATCH), 256, FIN_SMEM>>>(xcq, xcp);
    topk_reduce_kernel<<<dim3(16, BATCH, 2), 256>>>(valp, valq);
}

// round 7
// speedup vs baseline: 1.1766x; 1.1766x over previous
#include <cuda_runtime.h>
#include <cuda_bf16.h>
#include <math.h>
#include <cstdint>

#define BATCH 4
#define CDIM  256
#define NSP   4096
#define BN2   16777216
#define KTOT  768          // [hi | lo | hi] x [hi | hi | lo]
#define NCHUNK 12          // K chunks of 64

// ---------------------------------------------------------------------------
// Device scratch
// ---------------------------------------------------------------------------
__device__ float g_rowsum[BATCH * NSP];
__device__ float g_colsum[BATCH * NSP];
__device__ __nv_bfloat16 g_P[(size_t)BATCH * NSP * KTOT];
__device__ __nv_bfloat16 g_Q[(size_t)BATCH * NSP * KTOT];

// ---------------------------------------------------------------------------
// PTX helpers (sm_80-compatible: cp.async, ldmatrix, mma.sync)
// ---------------------------------------------------------------------------
__device__ __forceinline__ uint32_t smem_u32(const void* p) {
    uint32_t a;
    asm("{ .reg .u64 t; cvta.to.shared.u64 t, %1; cvt.u32.u64 %0, t; }"
        : "=r"(a) : "l"(p));
    return a;
}
__device__ __forceinline__ void cp16(uint32_t s, const void* g) {
    asm volatile("cp.async.cg.shared.global [%0], [%1], 16;" :: "r"(s), "l"(g));
}
__device__ __forceinline__ void cp_commit() {
    asm volatile("cp.async.commit_group;");
}
template <int N>
__device__ __forceinline__ void cp_wait() {
    asm volatile("cp.async.wait_group %0;" :: "n"(N));
}
__device__ __forceinline__ void ldmx4(uint32_t* r, uint32_t addr) {
    asm volatile("ldmatrix.sync.aligned.m8n8.x4.shared.b16 {%0,%1,%2,%3}, [%4];"
                 : "=r"(r[0]), "=r"(r[1]), "=r"(r[2]), "=r"(r[3]) : "r"(addr));
}
__device__ __forceinline__ void mma16816(float* d, const uint32_t* a, const uint32_t* b) {
    asm volatile(
        "mma.sync.aligned.m16n8k16.row.col.f32.bf16.bf16.f32 "
        "{%0,%1,%2,%3}, {%4,%5,%6,%7}, {%8,%9}, {%0,%1,%2,%3};"
        : "+f"(d[0]), "+f"(d[1]), "+f"(d[2]), "+f"(d[3])
        : "r"(a[0]), "r"(a[1]), "r"(a[2]), "r"(a[3]), "r"(b[0]), "r"(b[1]));
}

// ---------------------------------------------------------------------------
// Kernel 0: zero accumulators (re-zeroed every replay)
// ---------------------------------------------------------------------------
__global__ void zero_sums_kernel() {
    int i = blockIdx.x * 256 + threadIdx.x;
    g_rowsum[i] = 0.0f;
    g_colsum[i] = 0.0f;
}

// ---------------------------------------------------------------------------
// Kernel 1: prep — L2-normalize over channels, bf16 hi/lo split, K-major [m][768]
// ---------------------------------------------------------------------------
__global__ __launch_bounds__(256)
void prep_kernel(const float* __restrict__ xp, const float* __restrict__ xq) {
    __shared__ float tile[32][257];
    const int m0 = blockIdx.x * 32;
    const int b  = blockIdx.y;
    const int t  = threadIdx.x;
    const int w  = t >> 5, lane = t & 31;
    const bool isP = (blockIdx.z == 0);
    const float* src = isP ? xp : xq;
    __nv_bfloat16* dst = isP ? g_P : g_Q;

    #pragma unroll 8
    for (int it = 0; it < 32; it++) {
        int c = w + it * 8;
        tile[lane][c] = src[((size_t)b * CDIM + c) * NSP + m0 + lane];
    }
    __syncthreads();

    #pragma unroll
    for (int r = 0; r < 4; r++) {
        int row = w * 4 + r;
        float s = 0.0f;
        #pragma unroll
        for (int k = 0; k < 8; k++) {
            float v = tile[row][lane + 32 * k];
            s = fmaf(v, v, s);
        }
        #pragma unroll
        for (int off = 16; off > 0; off >>= 1)
            s += __shfl_down_sync(0xFFFFFFFFu, s, off);
        float invn = 1.0f / fmaxf(sqrtf(__shfl_sync(0xFFFFFFFFu, s, 0)), 1e-12f);

        size_t obase = ((size_t)b * NSP + m0 + row) * KTOT;
        #pragma unroll
        for (int k = 0; k < 8; k++) {
            int c = lane + 32 * k;
            float v = tile[row][c] * invn;
            __nv_bfloat16 hi = __float2bfloat16(v);
            __nv_bfloat16 lo = __float2bfloat16(v - __bfloat162float(hi));
            dst[obase + c] = hi;
            dst[obase + 256 + c] = isP ? lo : hi;
            dst[obase + 512 + c] = isP ? hi : lo;
        }
    }
}

// ---------------------------------------------------------------------------
// Kernel 2: HMMA GEMM (128x128, K=768) + exp epilogue  [R3 config, measured]
// ---------------------------------------------------------------------------
#define SMEM_BUFS  1024
#define SMEM_TOTAL (1024 + 4 * 16384)

__global__ __launch_bounds__(256, 2)
void gemm_exp_kernel(const float* __restrict__ alpha_p, float* __restrict__ out_e) {
    extern __shared__ char smem[];
    const uint32_t sbase = smem_u32(smem);
    float* srow = (float*)smem;
    float* scol = (float*)(smem + 512);

    const int t = threadIdx.x;
    const int w = t >> 5, lane = t & 31;
    const int b  = blockIdx.z;
    const int i0 = blockIdx.y * 128;
    const int j0 = blockIdx.x * 128;

    if (t < 128) { srow[t] = 0.0f; scol[t] = 0.0f; }

    const __nv_bfloat16* Abase = g_P + ((size_t)b * NSP + i0) * KTOT;
    const __nv_bfloat16* Bbase = g_Q + ((size_t)b * NSP + j0) * KTOT;

    auto load_chunk = [&](int c, int buf) {
        uint32_t aS = sbase + SMEM_BUFS + buf * 32768;
        uint32_t bS = aS + 16384;
        #pragma unroll
        for (int u = 0; u < 4; u++) {
            int f = t + 256 * u;
            uint32_t row = f >> 3, seg = f & 7;
            uint32_t off = row * 128 + ((seg ^ (row & 7)) << 4);
            cp16(aS + off, Abase + (size_t)row * KTOT + c * 64 + seg * 8);
            cp16(bS + off, Bbase + (size_t)row * KTOT + c * 64 + seg * 8);
        }
    };

    const int wm = w >> 2, wn = w & 3;
    const int r16 = lane & 15, ahi = lane >> 4;
    const int bn  = (lane & 7) + ((lane >> 4) << 3);
    const int bkl = (lane >> 3) & 1;

    float d[4][4][4] = {};

    load_chunk(0, 0);
    cp_commit();

    #pragma unroll 1
    for (int c = 0; c < NCHUNK; c++) {
        if (c < NCHUNK - 1) { load_chunk(c + 1, (c + 1) & 1); cp_commit(); }
        if (c < NCHUNK - 1) cp_wait<1>(); else cp_wait<0>();
        __syncthreads();

        uint32_t aS = sbase + SMEM_BUFS + (c & 1) * 32768;
        uint32_t bS = aS + 16384;

        #pragma unroll
        for (int kk = 0; kk < 4; kk++) {
            uint32_t afr[4][4];
            #pragma unroll
            for (int mt = 0; mt < 4; mt++) {
                uint32_t row = wm * 64 + mt * 16 + r16;
                uint32_t col = (((2 * kk + ahi) ^ (r16 & 7)) << 4);
                ldmx4(afr[mt], aS + row * 128 + col);
            }
            uint32_t bfr[4][2];
            #pragma unroll
            for (int np = 0; np < 2; np++) {
                uint32_t nrow = wn * 32 + np * 16 + bn;
                uint32_t col = (((2 * kk + bkl) ^ (bn & 7)) << 4);
                uint32_t q[4];
                ldmx4(q, bS + nrow * 128 + col);
                bfr[2 * np][0] = q[0]; bfr[2 * np][1] = q[1];
                bfr[2 * np + 1][0] = q[2]; bfr[2 * np + 1][1] = q[3];
            }
            #pragma unroll
            for (int mt = 0; mt < 4; mt++)
                #pragma unroll
                for (int nt = 0; nt < 4; nt++)
                    mma16816(d[mt][nt], afr[mt], bfr[nt]);
        }
        __syncthreads();
    }

    const float alpha = __ldg(alpha_p);
    const int g = lane >> 2, tg = lane & 3;
    float csum[4][2] = {};
    float* outb = out_e + (size_t)b * BN2;

    #pragma unroll
    for (int mt = 0; mt < 4; mt++) {
        float rs0 = 0.0f, rs1 = 0.0f;
        const int row0 = i0 + wm * 64 + mt * 16 + g;
        #pragma unroll
        for (int nt = 0; nt < 4; nt++) {
            float e0 = __expf(d[mt][nt][0] * alpha);
            float e1 = __expf(d[mt][nt][1] * alpha);
            float e2 = __expf(d[mt][nt][2] * alpha);
            float e3 = __expf(d[mt][nt][3] * alpha);
            rs0 += e0 + e1; rs1 += e2 + e3;
            csum[nt][0] += e0 + e2; csum[nt][1] += e1 + e3;
            const int colg = j0 + wn * 32 + nt * 8 + tg * 2;
            *(float2*)(outb + (size_t)row0 * NSP + colg)       = make_float2(e0, e1);
            *(float2*)(outb + (size_t)(row0 + 8) * NSP + colg) = make_float2(e2, e3);
        }
        rs0 += __shfl_xor_sync(0xFFFFFFFFu, rs0, 1);
        rs0 += __shfl_xor_sync(0xFFFFFFFFu, rs0, 2);
        rs1 += __shfl_xor_sync(0xFFFFFFFFu, rs1, 1);
        rs1 += __shfl_xor_sync(0xFFFFFFFFu, rs1, 2);
        if (tg == 0) {
            atomicAdd(&srow[wm * 64 + mt * 16 + g],     rs0);
            atomicAdd(&srow[wm * 64 + mt * 16 + g + 8], rs1);
        }
    }
    #pragma unroll
    for (int nt = 0; nt < 4; nt++)
        #pragma unroll
        for (int cc = 0; cc < 2; cc++) {
            float v = csum[nt][cc];
            v += __shfl_xor_sync(0xFFFFFFFFu, v, 4);
            v += __shfl_xor_sync(0xFFFFFFFFu, v, 8);
            v += __shfl_xor_sync(0xFFFFFFFFu, v, 16);
            if (g == 0) atomicAdd(&scol[wn * 32 + nt * 8 + tg * 2 + cc], v);
        }
    __syncthreads();
    if (t < 128) {
        atomicAdd(&g_rowsum[b * NSP + i0 + t], srow[t]);
        atomicAdd(&g_colsum[b * NSP + j0 + t], scol[t]);
    }
}

// ---------------------------------------------------------------------------
// top-3 helpers
// ---------------------------------------------------------------------------
__device__ __forceinline__ void top3_push(float v, float& v0, float& v1, float& v2) {
    if (v > v2) {
        if (v > v1) {
            v2 = v1;
            if (v > v0) { v1 = v0; v0 = v; } else { v1 = v; }
        } else v2 = v;
    }
}
__device__ __forceinline__ void warp_reduce_top3(float& v0, float& v1, float& v2) {
    #pragma unroll
    for (int off = 16; off > 0; off >>= 1) {
        float u0 = __shfl_down_sync(0xFFFFFFFFu, v0, off);
        float u1 = __shfl_down_sync(0xFFFFFFFFu, v1, off);
        float u2 = __shfl_down_sync(0xFFFFFFFFu, v2, off);
        top3_push(u0, v0, v1, v2);
        top3_push(u1, v0, v1, v2);
        top3_push(u2, v0, v1, v2);
    }
}

// ---------------------------------------------------------------------------
// Kernel 3: row pass (R3, measured 93us @65% DRAM). e -> x_c in place;
// fused row top-3 -> valp.
// ---------------------------------------------------------------------------
__global__ __launch_bounds__(256)
void rowpass_kernel(float* __restrict__ xcq, float* __restrict__ valp) {
    __shared__ float sinvc[NSP];
    const int b = blockIdx.y;
    const int t = threadIdx.x;
    for (int j = t; j < NSP; j += 256)
        sinvc[j] = 1.0f / g_colsum[b * NSP + j];
    __syncthreads();

    const int w = t >> 5, lane = t & 31;
    const int i = blockIdx.x * 8 + w;
    const float invr = 1.0f / g_rowsum[b * NSP + i];
    float* row = xcq + (size_t)b * BN2 + (size_t)i * NSP;

    float v0 = -1e30f, v1 = -1e30f, v2 = -1e30f;
    for (int jb = lane * 4; jb < NSP; jb += 128) {
        float4 e  = *reinterpret_cast<float4*>(row + jb);
        float4 si = *reinterpret_cast<float4*>(&sinvc[jb]);
        float x0 = e.x * e.x * invr * si.x;
        float x1 = e.y * e.y * invr * si.y;
        float x2 = e.z * e.z * invr * si.z;
        float x3 = e.w * e.w * invr * si.w;
        *reinterpret_cast<float4*>(row + jb) = make_float4(x0, x1, x2, x3);
        top3_push(x0, v0, v1, v2);
        top3_push(x1, v0, v1, v2);
        top3_push(x2, v0, v1, v2);
        top3_push(x3, v0, v1, v2);
    }
    warp_reduce_top3(v0, v1, v2);
    if (lane == 0) {
        valp[b * 3 * NSP + 0 * NSP + i] = v0;
        valp[b * 3 * NSP + 1 * NSP + i] = v1;
        valp[b * 3 * NSP + 2 * NSP + i] = v2;
    }
}

// ---------------------------------------------------------------------------
// Kernel 4: column pass — 32-col blocks, 64-row double-buffered smem tiles.
// Fully coalesced reads (warp = 32 contiguous cols) AND writes (128B column
// runs). One barrier per 64 rows. Each warp owns 4 complete columns ->
// valq computed directly (no partials).
// ---------------------------------------------------------------------------
__global__ __launch_bounds__(256)
void colpass_kernel(const float* __restrict__ xcq,
                    float* __restrict__ xcp,
                    float* __restrict__ valq) {
    __shared__ float tile[2][64][33];
    const int b  = blockIdx.y;
    const int j0 = blockIdx.x * 32;
    const int t  = threadIdx.x;
    const int w  = t >> 5, lane = t & 31;
    const int lr = t >> 5;                 // load row base 0..7
    const float* src = xcq + (size_t)b * BN2;
    float*       dst = xcp + (size_t)b * BN2;

    float c0[4], c1[4], c2[4];
    #pragma unroll
    for (int k = 0; k < 4; k++) { c0[k] = -1e30f; c1[k] = -1e30f; c2[k] = -1e30f; }

    // load 64 rows starting at ic into buffer bf
    auto load = [&](int ic, int bf) {
        #pragma unroll
        for (int u = 0; u < 8; u++) {
            int r = lr + u * 8;
            tile[bf][r][lane] = src[(size_t)(ic + r) * NSP + j0 + lane];
        }
    };

    load(0, 0);
    int bf = 0;

    #pragma unroll 1
    for (int ic = 0; ic < NSP; ic += 64) {
        __syncthreads();
        if (ic + 64 < NSP) load(ic + 64, bf ^ 1);

        // write phase: warp w owns columns w*4..w*4+3
        #pragma unroll
        for (int k = 0; k < 4; k++) {
            const int col = w * 4 + k;
            float va = tile[bf][lane][col];
            float vb = tile[bf][32 + lane][col];
            dst[(size_t)(j0 + col) * NSP + ic + lane]      = va;
            dst[(size_t)(j0 + col) * NSP + ic + 32 + lane] = vb;
            top3_push(va, c0[k], c1[k], c2[k]);
            top3_push(vb, c0[k], c1[k], c2[k]);
        }
        bf ^= 1;
    }

    #pragma unroll
    for (int k = 0; k < 4; k++) {
        float v0 = c0[k], v1 = c1[k], v2 = c2[k];
        warp_reduce_top3(v0, v1, v2);
        if (lane == 0) {
            const int j = j0 + w * 4 + k;
            valq[b * 3 * NSP + 0 * NSP + j] = v0;
            valq[b * 3 * NSP + 1 * NSP + j] = v1;
            valq[b * 3 * NSP + 2 * NSP + j] = v2;
        }
    }
}

// ---------------------------------------------------------------------------
extern "C" void kernel_launch(void* const* d_in, const int* in_sizes, int n_in,
                              void* d_out, int out_size) {
    const float* xp    = (const float*)d_in[0];
    const float* xq    = (const float*)d_in[1];
    const float* alpha = (const float*)d_in[2];

    float* valp = (float*)d_out;
    float* valq = valp + BATCH * 3 * NSP;
    float* xcp  = valq + BATCH * 3 * NSP;
    float* xcq  = xcp + (size_t)BATCH * BN2;

    cudaFuncSetAttribute(gemm_exp_kernel,
                         cudaFuncAttributeMaxDynamicSharedMemorySize, SMEM_TOTAL);

    zero_sums_kernel<<<64, 256>>>();
    prep_kernel<<<dim3(128, BATCH, 2), 256>>>(xp, xq);
    gemm_exp_kernel<<<dim3(32, 32, BATCH), 256, SMEM_TOTAL>>>(alpha, xcq);
    rowpass_kernel<<<dim3(512, BATCH), 256>>>(xcq, valp);
    colpass_kernel<<<dim3(128, BATCH), 256>>>(xcq, xcp, valq);
}